// round 2
// baseline (speedup 1.0000x reference)
#include <cuda_runtime.h>
#include <math.h>

// Problem constants
#define Bb   16
#define Tt   2048
#define Cc   512
#define Hh   4
#define DHd  128
#define Nn   (Bb*Tt)    // 32768 tokens
#define N2   (Nn*2)     // 65536 token-device rows

// ---------------- device scratch (no allocations allowed) ----------------
__device__ float g_QKV[N2 * 1536];      // 400 MB: q|k|v per token-device row
__device__ float g_ctx[N2 * 512];       // 134 MB: attention context
__device__ float g_tmp[512 * 512];      // fold scratch
__device__ float g_Mcat[512 * 1024];    // [M0 | M1] folded post-attention weights
__device__ float g_u[2 * 512];          // folded bias intermediates
__device__ float g_bconst[512];         // folded output bias

// =========================================================================
// Fold kernels: M0 = WoutL @ Wp @ Wo, M1 = WoutR @ Wi @ Wo, bconst
// =========================================================================

// Generic 512x512x512 row-major GEMM: C[m,n] = sum_k A[m*lda+k] * B[k*512+n]
__global__ void k_fold_gemm(const float* __restrict__ A, int lda,
                            const float* __restrict__ Bm,
                            int useTmpB, int writeMcat, int coff)
{
    __shared__ float As[32][33];
    __shared__ float Bs[32][33];
    const float* Bp = useTmpB ? g_tmp : Bm;
    float* Cp;
    int ldc;
    if (writeMcat) { Cp = g_Mcat + coff; ldc = 1024; }
    else           { Cp = g_tmp;         ldc = 512;  }

    int tx = threadIdx.x, ty = threadIdx.y;
    int row = blockIdx.y * 32 + ty;
    int col = blockIdx.x * 32 + tx;
    float acc = 0.f;
    for (int k0 = 0; k0 < 512; k0 += 32) {
        As[ty][tx] = A[row * lda + k0 + tx];
        Bs[ty][tx] = Bp[(k0 + ty) * 512 + col];
        __syncthreads();
        #pragma unroll
        for (int kk = 0; kk < 32; kk++) acc += As[ty][kk] * Bs[kk][tx];
        __syncthreads();
    }
    Cp[row * ldc + col] = acc;
}

// u[d][j] = sum_l W_d[j,l]*out_proj_b[l] + b_d[j]   (d=0: phone, d=1: imu)
__global__ void k_fold_u(const float* __restrict__ phone_w, const float* __restrict__ phone_b,
                         const float* __restrict__ imu_w,   const float* __restrict__ imu_b,
                         const float* __restrict__ out_proj_b)
{
    int idx = blockIdx.x * blockDim.x + threadIdx.x;
    if (idx >= 1024) return;
    int d = idx >> 9, j = idx & 511;
    const float* W  = d ? imu_w : phone_w;
    const float* bb = d ? imu_b : phone_b;
    float s = bb[j];
    for (int l = 0; l < 512; l++) s += W[j * 512 + l] * out_proj_b[l];
    g_u[idx] = s;
}

// bconst[o] = WoutL[o,:].u0 + WoutR[o,:].u1 + output_b[o]; also zero avg region
__global__ void k_fold_bconst(const float* __restrict__ output_w,
                              const float* __restrict__ output_b,
                              float* __restrict__ d_avg)
{
    int o = blockIdx.x * blockDim.x + threadIdx.x;
    if (o < 64) d_avg[o] = 0.f;
    if (o >= 512) return;
    float s = output_b[o];
    for (int j = 0; j < 512; j++) {
        s += output_w[o * 1024 + j]       * g_u[j];
        s += output_w[o * 1024 + 512 + j] * g_u[512 + j];
    }
    g_bconst[o] = s;
}

// =========================================================================
// GEMM1: QKV = (x transposed + emb) @ in_proj_w^T + in_proj_b
//   rows = token-device pairs; A-tile built on the fly from x (B,C,2,T)
//   tile: 128 rows (64 tokens x 2 dev, dev-major) x 128 cols, BK=16
// =========================================================================
__global__ __launch_bounds__(256) void k_qkv(const float* __restrict__ x,
                                             const float* __restrict__ emb,
                                             const float* __restrict__ W,
                                             const float* __restrict__ bias)
{
    __shared__ float As[16][132];
    __shared__ float Bs[16][132];
    int tid = threadIdx.x;
    int n0 = blockIdx.y * 64;        // first token of tile (never crosses batch: 2048 % 64 == 0)
    int j0 = blockIdx.x * 128;
    int b  = n0 >> 11;
    int t0 = n0 & 2047;

    int ar = tid & 127;              // tile row for A loads
    int d  = ar >> 6, tl = ar & 63;
    const float* xbase = x + (size_t)b * 2097152 + d * 2048 + t0 + tl;
    const float* embd  = emb + d * 512;
    int ka = tid >> 7;               // 0/1
    int kb = tid & 15;
    int jb = tid >> 4;               // 0..15
    int ty = tid >> 4, tx = tid & 15;

    float acc[8][8];
    #pragma unroll
    for (int i = 0; i < 8; i++)
        #pragma unroll
        for (int j = 0; j < 8; j++) acc[i][j] = 0.f;

    for (int k0 = 0; k0 < 512; k0 += 16) {
        #pragma unroll
        for (int i = 0; i < 8; i++) {
            int kk = ka + i * 2;
            int c  = k0 + kk;
            As[kk][ar] = __ldg(&xbase[(size_t)c * 4096]) + embd[c];
        }
        #pragma unroll
        for (int i = 0; i < 8; i++) {
            int j = jb + i * 16;
            Bs[kb][j] = W[(size_t)(j0 + j) * 512 + k0 + kb];
        }
        __syncthreads();
        #pragma unroll
        for (int kk = 0; kk < 16; kk++) {
            float a[8], bv[8];
            *(float4*)&a[0]  = *(const float4*)&As[kk][ty * 8];
            *(float4*)&a[4]  = *(const float4*)&As[kk][ty * 8 + 4];
            *(float4*)&bv[0] = *(const float4*)&Bs[kk][tx * 8];
            *(float4*)&bv[4] = *(const float4*)&Bs[kk][tx * 8 + 4];
            #pragma unroll
            for (int i = 0; i < 8; i++)
                #pragma unroll
                for (int j = 0; j < 8; j++) acc[i][j] += a[i] * bv[j];
        }
        __syncthreads();
    }
    #pragma unroll
    for (int i = 0; i < 8; i++) {
        int r  = ty * 8 + i;
        int n2 = 2 * (n0 + (r & 63)) + (r >> 6);
        float* outp = g_QKV + (size_t)n2 * 1536 + j0 + tx * 8;
        #pragma unroll
        for (int j = 0; j < 8; j++)
            outp[j] = acc[i][j] + bias[j0 + tx * 8 + j];
    }
}

// =========================================================================
// Attention: per (token, head) — 2x2 scores, softmax, ctx = P @ V
// 256 threads = 2 tokens x 4 heads(warps). Also accumulate avg_attention.
// =========================================================================
__global__ __launch_bounds__(256) void k_attn(float* __restrict__ d_avg)
{
    __shared__ float sp[4];
    int tid = threadIdx.x;
    if (tid < 4) sp[tid] = 0.f;
    __syncthreads();

    int n    = blockIdx.x * 2 + (tid >> 7);
    int h    = (tid >> 5) & 3;
    int lane = tid & 31;

    const float* base = g_QKV + (size_t)(2 * n) * 1536 + h * 128 + lane * 4;
    float4 q0  = *(const float4*)(base);
    float4 q1  = *(const float4*)(base + 1536);
    float4 k0v = *(const float4*)(base + 512);
    float4 k1v = *(const float4*)(base + 512 + 1536);
    float4 v0  = *(const float4*)(base + 1024);
    float4 v1  = *(const float4*)(base + 1024 + 1536);

    float s00 = q0.x*k0v.x + q0.y*k0v.y + q0.z*k0v.z + q0.w*k0v.w;
    float s01 = q0.x*k1v.x + q0.y*k1v.y + q0.z*k1v.z + q0.w*k1v.w;
    float s10 = q1.x*k0v.x + q1.y*k0v.y + q1.z*k0v.z + q1.w*k0v.w;
    float s11 = q1.x*k1v.x + q1.y*k1v.y + q1.z*k1v.z + q1.w*k1v.w;
    #pragma unroll
    for (int off = 16; off; off >>= 1) {
        s00 += __shfl_xor_sync(0xffffffffu, s00, off);
        s01 += __shfl_xor_sync(0xffffffffu, s01, off);
        s10 += __shfl_xor_sync(0xffffffffu, s10, off);
        s11 += __shfl_xor_sync(0xffffffffu, s11, off);
    }
    const float sc = 0.08838834764831845f;   // 1/sqrt(128)
    s00 *= sc; s01 *= sc; s10 *= sc; s11 *= sc;

    float m0 = fmaxf(s00, s01);
    float e00 = expf(s00 - m0), e01 = expf(s01 - m0);
    float r0 = 1.f / (e00 + e01);
    float p00 = e00 * r0, p01 = e01 * r0;
    float m1 = fmaxf(s10, s11);
    float e10 = expf(s10 - m1), e11 = expf(s11 - m1);
    float r1 = 1.f / (e10 + e11);
    float p10 = e10 * r1, p11 = e11 * r1;

    float* ctxp = g_ctx + (size_t)(2 * n) * 512 + h * 128 + lane * 4;
    float4 c0, c1;
    c0.x = p00*v0.x + p01*v1.x; c0.y = p00*v0.y + p01*v1.y;
    c0.z = p00*v0.z + p01*v1.z; c0.w = p00*v0.w + p01*v1.w;
    c1.x = p10*v0.x + p11*v1.x; c1.y = p10*v0.y + p11*v1.y;
    c1.z = p10*v0.z + p11*v1.z; c1.w = p10*v0.w + p11*v1.w;
    *(float4*)ctxp         = c0;
    *(float4*)(ctxp + 512) = c1;

    if (lane == 0) {
        atomicAdd(&sp[0], p00);
        atomicAdd(&sp[1], p01);
        atomicAdd(&sp[2], p10);
        atomicAdd(&sp[3], p11);
    }
    __syncthreads();
    if (tid < 4) {
        int b = (blockIdx.x * 2) >> 11;           // both tokens share b
        atomicAdd(&d_avg[b * 4 + tid], sp[tid] * (1.0f / 8192.0f));  // / (H*T)
    }
}

// =========================================================================
// GEMM2: out[n,o] = ctx(N x 1024) @ Mcat^T + bconst; written as (B,C,T)
//   tile: 128 tokens x 128 output cols, K=1024, BK=16
// =========================================================================
__global__ __launch_bounds__(256) void k_out(float* __restrict__ out)
{
    __shared__ float As[16][132];
    __shared__ float Bs[16][132];
    int tid = threadIdx.x;
    int n0 = blockIdx.y * 128;       // 2048 % 128 == 0 -> never crosses batch
    int o0 = blockIdx.x * 128;
    int kb = tid & 15;
    int rb = tid >> 4;
    int ty = tid >> 4, tx = tid & 15;

    float acc[8][8];
    #pragma unroll
    for (int i = 0; i < 8; i++)
        #pragma unroll
        for (int j = 0; j < 8; j++) acc[i][j] = 0.f;

    for (int k0 = 0; k0 < 1024; k0 += 16) {
        #pragma unroll
        for (int i = 0; i < 8; i++) {
            int r = rb + i * 16;
            As[kb][r] = g_ctx [(size_t)(n0 + r) * 1024 + k0 + kb];
            Bs[kb][r] = g_Mcat[(size_t)(o0 + r) * 1024 + k0 + kb];
        }
        __syncthreads();
        #pragma unroll
        for (int kk = 0; kk < 16; kk++) {
            float a[8], bv[8];
            *(float4*)&a[0]  = *(const float4*)&As[kk][ty * 8];
            *(float4*)&a[4]  = *(const float4*)&As[kk][ty * 8 + 4];
            *(float4*)&bv[0] = *(const float4*)&Bs[kk][tx * 8];
            *(float4*)&bv[4] = *(const float4*)&Bs[kk][tx * 8 + 4];
            #pragma unroll
            for (int i = 0; i < 8; i++)
                #pragma unroll
                for (int j = 0; j < 8; j++) acc[i][j] += a[i] * bv[j];
        }
        __syncthreads();
    }
    int b  = n0 >> 11;
    int t0 = n0 & 2047;
    #pragma unroll
    for (int i = 0; i < 8; i++) {
        int t = t0 + ty * 8 + i;
        #pragma unroll
        for (int j = 0; j < 8; j++) {
            int o = o0 + tx * 8 + j;
            out[(size_t)b * 1048576 + (size_t)o * 2048 + t] = acc[i][j] + g_bconst[o];
        }
    }
}

// =========================================================================
extern "C" void kernel_launch(void* const* d_in, const int* in_sizes, int n_in,
                              void* d_out, int out_size)
{
    (void)in_sizes; (void)n_in; (void)out_size;
    const float* x      = (const float*)d_in[0];
    const float* emb    = (const float*)d_in[1];
    const float* in_w   = (const float*)d_in[2];
    const float* in_b   = (const float*)d_in[3];
    const float* out_w  = (const float*)d_in[4];
    const float* out_b  = (const float*)d_in[5];
    const float* ph_w   = (const float*)d_in[6];
    const float* ph_b   = (const float*)d_in[7];
    const float* im_w   = (const float*)d_in[8];
    const float* im_b   = (const float*)d_in[9];
    const float* o2_w   = (const float*)d_in[10];
    const float* o2_b   = (const float*)d_in[11];
    float* out   = (float*)d_out;
    float* d_avg = out + (size_t)Bb * Cc * Tt;   // avg_attention after main output

    dim3 fg(16, 16), fb(32, 32);
    // T0 = phone_w @ out_proj_w -> tmp ; M0 = WoutL @ T0 -> Mcat[:, :512]
    k_fold_gemm<<<fg, fb>>>(ph_w, 512, out_w, 0, 0, 0);
    k_fold_gemm<<<fg, fb>>>(o2_w, 1024, nullptr, 1, 1, 0);
    // T1 = imu_w @ out_proj_w -> tmp ; M1 = WoutR @ T1 -> Mcat[:, 512:]
    k_fold_gemm<<<fg, fb>>>(im_w, 512, out_w, 0, 0, 0);
    k_fold_gemm<<<fg, fb>>>(o2_w + 512, 1024, nullptr, 1, 1, 512);
    // folded biases + zero avg region
    k_fold_u<<<4, 256>>>(ph_w, ph_b, im_w, im_b, out_b);
    k_fold_bconst<<<2, 256>>>(o2_w, o2_b, d_avg);

    // main pipeline
    k_qkv <<<dim3(12, 512), 256>>>(x, emb, in_w, in_b);
    k_attn<<<Nn / 2, 256>>>(d_avg);
    k_out <<<dim3(4, 256), 256>>>(out);
}

// round 9
// speedup vs baseline: 1.9637x; 1.9637x over previous
#include <cuda_runtime.h>
#include <cuda_bf16.h>
#include <stdint.h>
#include <math.h>

#define Nn 32768
#define N2 65536

// ---------------- device scratch (no allocations allowed) ----------------
__device__ __align__(256) __nv_bfloat16 g_xh[(size_t)N2*512];
__device__ __align__(256) __nv_bfloat16 g_xl[(size_t)N2*512];
__device__ __align__(256) __nv_bfloat16 g_wh[1536*512];
__device__ __align__(256) __nv_bfloat16 g_wl[1536*512];
__device__ __align__(256) float g_QKV[(size_t)N2*1536];
__device__ __align__(256) __nv_bfloat16 g_ch[(size_t)Nn*1024];
__device__ __align__(256) __nv_bfloat16 g_cl[(size_t)Nn*1024];
__device__ __align__(256) float g_tmp[2*512*512];
__device__ __align__(256) float g_Mcat[512*1024];
__device__ __align__(256) __nv_bfloat16 g_mh[512*1024];
__device__ __align__(256) __nv_bfloat16 g_ml[512*1024];
__device__ float g_u[1024];
__device__ float g_bconst[512];

// ---------------- PTX helpers (sm_80-baseline ISA only) ----------------
__device__ __forceinline__ unsigned smem_u32(const void* p){
    unsigned a;
    asm("{ .reg .u64 t; cvta.to.shared.u64 t, %1; cvt.u32.u64 %0, t; }" : "=r"(a) : "l"(p));
    return a;
}
#define CP16(smem_addr, gptr) \
    asm volatile("cp.async.cg.shared.global [%0], [%1], 16;" :: "r"(smem_addr), "l"(gptr))
#define CP_COMMIT() asm volatile("cp.async.commit_group;" ::: "memory")
#define LDSM4(r, addr) \
    asm volatile("ldmatrix.sync.aligned.m8n8.x4.shared.b16 {%0,%1,%2,%3}, [%4];" \
        : "=r"((r)[0]), "=r"((r)[1]), "=r"((r)[2]), "=r"((r)[3]) : "r"(addr))
#define MMA16816(d, a, b0, b1) \
    asm volatile("mma.sync.aligned.m16n8k16.row.col.f32.bf16.bf16.f32 " \
        "{%0,%1,%2,%3}, {%4,%5,%6,%7}, {%8,%9}, {%0,%1,%2,%3};" \
        : "+f"((d)[0]), "+f"((d)[1]), "+f"((d)[2]), "+f"((d)[3]) \
        : "r"((a)[0]), "r"((a)[1]), "r"((a)[2]), "r"((a)[3]), "r"(b0), "r"(b1))

// Tile geometry: CTA 128(M) x 128(N), K-chunk 32. Smem rows padded to 80B.
#define LDS_ROW 80
#define TILE_BYTES (128*LDS_ROW)        // 10240 per matrix
#define BUF_BYTES  (2*TILE_BYTES)       // A + B per buffer

// =========================================================================
// Unified HMMA GEMM. D[m][n] = sum_k A[m][k]*B[n][k] over 3 bf16-split segs.
// mode 0: A = xe (M=n2 rows), B = in_proj W (N=j)  -> QKV[n2][j] + bias[j]
// mode 1: A = Mcat (M=o),     B = ctx (N=token)    -> out[b][o][t] + bconst[o]
// =========================================================================
__global__ __launch_bounds__(256) void k_mma(int mode, const float* __restrict__ bias,
                                             float* __restrict__ out)
{
    __shared__ __align__(128) char smem[2*BUF_BYTES];
    unsigned sb = smem_u32(smem);
    int tid = threadIdx.x, wid = tid >> 5, lane = tid & 31;

    const __nv_bfloat16* Ah = mode ? g_mh : g_xh;
    const __nv_bfloat16* Al = mode ? g_ml : g_xl;
    const __nv_bfloat16* Bh = mode ? g_ch : g_wh;
    const __nv_bfloat16* Bl = mode ? g_cl : g_wl;
    int ldk  = mode ? 1024 : 512;
    int per  = mode ? 32 : 16;          // K-chunks per segment
    int nblk = 3 * per;

    int m0 = blockIdx.y * 128;
    int n0 = blockIdx.x * 128;

    // cp.async thread mapping: 2 rows per matrix per thread
    int cr = tid >> 2, cc = tid & 3;    // row 0..63 (+64), 16B col 0..3

    float acc[2][8][4];
    #pragma unroll
    for (int mt = 0; mt < 2; mt++)
        #pragma unroll
        for (int nt = 0; nt < 8; nt++)
            #pragma unroll
            for (int i = 0; i < 4; i++) acc[mt][nt][i] = 0.f;

    int wm = wid >> 1, wn = wid & 1;    // warp grid 4x2 -> warp tile 32x64

    // ---- prefetch chunk 0 ----
    {
        const __nv_bfloat16* Ap = Ah;
        const __nv_bfloat16* Bp = Bh;
        unsigned sa = sb, sB = sb + TILE_BYTES;
        #pragma unroll
        for (int i = 0; i < 2; i++){
            int r = cr + i*64;
            CP16(sa + r*LDS_ROW + cc*16, Ap + (size_t)(m0 + r)*ldk + cc*8);
            CP16(sB + r*LDS_ROW + cc*16, Bp + (size_t)(n0 + r)*ldk + cc*8);
        }
        CP_COMMIT();
    }

    for (int blk = 0; blk < nblk; blk++){
        int buf = blk & 1;
        if (blk + 1 < nblk){
            int nb  = blk + 1;
            int seg = nb / per, k0 = (nb % per) * 32;
            const __nv_bfloat16* Ap = (seg == 1) ? Al : Ah;
            const __nv_bfloat16* Bp = (seg == 2) ? Bl : Bh;
            unsigned sa = sb + (buf^1)*BUF_BYTES, sB = sa + TILE_BYTES;
            #pragma unroll
            for (int i = 0; i < 2; i++){
                int r = cr + i*64;
                CP16(sa + r*LDS_ROW + cc*16, Ap + (size_t)(m0 + r)*ldk + k0 + cc*8);
                CP16(sB + r*LDS_ROW + cc*16, Bp + (size_t)(n0 + r)*ldk + k0 + cc*8);
            }
            CP_COMMIT();
            asm volatile("cp.async.wait_group 1;" ::: "memory");
        } else {
            asm volatile("cp.async.wait_group 0;" ::: "memory");
        }
        __syncthreads();

        // ---- compute chunk (2 x k16) ----
        unsigned sa = sb + buf*BUF_BYTES, sB = sa + TILE_BYTES;
        int lrow = lane & 15, lcol = lane >> 4;
        #pragma unroll
        for (int kk = 0; kk < 2; kk++){
            unsigned ra[2][4], rb[4][4];
            #pragma unroll
            for (int mt = 0; mt < 2; mt++){
                unsigned ad = sa + (wm*32 + mt*16 + lrow)*LDS_ROW + (kk*2 + lcol)*16;
                LDSM4(ra[mt], ad);
            }
            #pragma unroll
            for (int p = 0; p < 4; p++){
                unsigned ad = sB + (wn*64 + p*16 + lrow)*LDS_ROW + (kk*2 + lcol)*16;
                LDSM4(rb[p], ad);
            }
            #pragma unroll
            for (int mt = 0; mt < 2; mt++)
                #pragma unroll
                for (int nt = 0; nt < 8; nt++){
                    int p = nt >> 1, w = nt & 1;
                    MMA16816(acc[mt][nt], ra[mt], rb[p][w], rb[p][w + 2]);
                }
        }
        __syncthreads();
    }

    // ---- epilogue: float2 stores along contiguous N ----
    int tr = lane >> 2, tc = lane & 3;
    #pragma unroll
    for (int mt = 0; mt < 2; mt++){
        #pragma unroll
        for (int nt = 0; nt < 8; nt++){
            float* d = acc[mt][nt];
            int gm0 = m0 + wm*32 + mt*16 + tr;
            int gn  = n0 + wn*64 + nt*8 + tc*2;
            if (mode == 0){
                float2 bv = *(const float2*)&bias[gn];
                float2 v0 = { d[0] + bv.x, d[1] + bv.y };
                float2 v1 = { d[2] + bv.x, d[3] + bv.y };
                *(float2*)&g_QKV[(size_t)gm0*1536 + gn]       = v0;
                *(float2*)&g_QKV[(size_t)(gm0+8)*1536 + gn]   = v1;
            } else {
                int b = gn >> 11, t = gn & 2047;
                float b0 = g_bconst[gm0], b1 = g_bconst[gm0 + 8];
                float* ob = out + (size_t)b*1048576 + t;
                float2 v0 = { d[0] + b0, d[1] + b0 };
                float2 v1 = { d[2] + b1, d[3] + b1 };
                *(float2*)&ob[(size_t)gm0*2048]     = v0;
                *(float2*)&ob[(size_t)(gm0+8)*2048] = v1;
            }
        }
    }
}

// =========================================================================
// Attention (fp32 SIMT): 2x2 softmax per (token, head); ctx -> bf16 hi/lo
// =========================================================================
__global__ __launch_bounds__(256) void k_attn(float* __restrict__ d_avg)
{
    __shared__ float sp[4];
    int tid = threadIdx.x;
    if (tid < 4) sp[tid] = 0.f;
    __syncthreads();

    int n    = blockIdx.x * 2 + (tid >> 7);
    int h    = (tid >> 5) & 3;
    int lane = tid & 31;

    const float* base = g_QKV + (size_t)(2 * n) * 1536 + h * 128 + lane * 4;
    float4 q0  = *(const float4*)(base);
    float4 q1  = *(const float4*)(base + 1536);
    float4 k0v = *(const float4*)(base + 512);
    float4 k1v = *(const float4*)(base + 512 + 1536);
    float4 v0  = *(const float4*)(base + 1024);
    float4 v1  = *(const float4*)(base + 1024 + 1536);

    float s00 = q0.x*k0v.x + q0.y*k0v.y + q0.z*k0v.z + q0.w*k0v.w;
    float s01 = q0.x*k1v.x + q0.y*k1v.y + q0.z*k1v.z + q0.w*k1v.w;
    float s10 = q1.x*k0v.x + q1.y*k0v.y + q1.z*k0v.z + q1.w*k0v.w;
    float s11 = q1.x*k1v.x + q1.y*k1v.y + q1.z*k1v.z + q1.w*k1v.w;
    #pragma unroll
    for (int off = 16; off; off >>= 1) {
        s00 += __shfl_xor_sync(0xffffffffu, s00, off);
        s01 += __shfl_xor_sync(0xffffffffu, s01, off);
        s10 += __shfl_xor_sync(0xffffffffu, s10, off);
        s11 += __shfl_xor_sync(0xffffffffu, s11, off);
    }
    const float sc = 0.08838834764831845f;
    s00 *= sc; s01 *= sc; s10 *= sc; s11 *= sc;

    float m0 = fmaxf(s00, s01);
    float e00 = expf(s00 - m0), e01 = expf(s01 - m0);
    float r0 = 1.f / (e00 + e01);
    float p00 = e00 * r0, p01 = e01 * r0;
    float m1 = fmaxf(s10, s11);
    float e10 = expf(s10 - m1), e11 = expf(s11 - m1);
    float r1 = 1.f / (e10 + e11);
    float p10 = e10 * r1, p11 = e11 * r1;

    float c0[4], c1[4];
    c0[0] = p00*v0.x + p01*v1.x; c0[1] = p00*v0.y + p01*v1.y;
    c0[2] = p00*v0.z + p01*v1.z; c0[3] = p00*v0.w + p01*v1.w;
    c1[0] = p10*v0.x + p11*v1.x; c1[1] = p10*v0.y + p11*v1.y;
    c1[2] = p10*v0.z + p11*v1.z; c1[3] = p10*v0.w + p11*v1.w;

    int cb = n * 1024 + h * 128 + lane * 4;   // ctx row = token, 1024-wide [dev0|dev1]
    #pragma unroll
    for (int dv = 0; dv < 2; dv++){
        const float* cv = dv ? c1 : c0;
        size_t idx = (size_t)cb + dv * 512;
        __nv_bfloat16 hh[4], ll[4];
        #pragma unroll
        for (int i = 0; i < 4; i++){
            hh[i] = __float2bfloat16(cv[i]);
            ll[i] = __float2bfloat16(cv[i] - __bfloat162float(hh[i]));
        }
        *(uint2*)(&g_ch[idx]) = *(uint2*)hh;
        *(uint2*)(&g_cl[idx]) = *(uint2*)ll;
    }

    if (lane == 0) {
        atomicAdd(&sp[0], p00);
        atomicAdd(&sp[1], p01);
        atomicAdd(&sp[2], p10);
        atomicAdd(&sp[3], p11);
    }
    __syncthreads();
    if (tid < 4) {
        int b = (blockIdx.x * 2) >> 11;
        atomicAdd(&d_avg[b * 4 + tid], sp[tid] * (1.0f / 8192.0f));
    }
}

// =========================================================================
// Prep: xe = transpose(x) + emb -> bf16 hi/lo, rows n2 = 2*(b*2048+t)+d
// =========================================================================
__global__ __launch_bounds__(256) void k_prep_x(const float* __restrict__ x,
                                                const float* __restrict__ emb)
{
    __shared__ float sm[32][33];
    int tx = threadIdx.x & 31, ty = threadIdx.x >> 5;
    int t0 = blockIdx.x * 32, c0 = blockIdx.y * 32;
    int b = blockIdx.z >> 1, d = blockIdx.z & 1;
    #pragma unroll
    for (int i = 0; i < 4; i++){
        int c = c0 + ty + i*8;
        sm[ty + i*8][tx] = x[((size_t)(b*512 + c)*2 + d)*2048 + t0 + tx];
    }
    __syncthreads();
    #pragma unroll
    for (int i = 0; i < 4; i++){
        int t = t0 + ty + i*8;
        int c = c0 + tx;
        float v = sm[tx][ty + i*8] + emb[d*512 + c];
        __nv_bfloat16 h = __float2bfloat16(v);
        size_t idx = (size_t)(2*(b*2048 + t) + d)*512 + c;
        g_xh[idx] = h;
        g_xl[idx] = __float2bfloat16(v - __bfloat162float(h));
    }
}

// split fp32 -> bf16 hi/lo. which 0: srcp -> wh/wl ; which 1: g_Mcat -> mh/ml
__global__ void k_split(const float* __restrict__ srcp, int which, int n)
{
    int i = blockIdx.x * 256 + threadIdx.x;
    if (i >= n) return;
    const float* src = which ? g_Mcat : srcp;
    float v = src[i];
    __nv_bfloat16 h = __float2bfloat16(v);
    if (which){ g_mh[i] = h; g_ml[i] = __float2bfloat16(v - __bfloat162float(h)); }
    else      { g_wh[i] = h; g_wl[i] = __float2bfloat16(v - __bfloat162float(h)); }
}

// =========================================================================
// Fold: C[m,n] = sum_k A[m*lda+k]*B[k*512+n], 64x64 tile, 4x4/thread, z-batched
// =========================================================================
__global__ __launch_bounds__(256) void k_fold(const float* __restrict__ A0,
                                              const float* __restrict__ A1, int lda,
                                              const float* __restrict__ Bext,
                                              int useTmp, int toMcat)
{
    __shared__ float As[16][68], Bs[16][68];
    int z = blockIdx.z;
    const float* A = z ? A1 : A0;
    const float* B = useTmp ? (g_tmp + z*262144) : Bext;
    float* C; int ldc;
    if (toMcat){ C = g_Mcat + z*512; ldc = 1024; }
    else       { C = g_tmp + z*262144; ldc = 512; }

    int tid = threadIdx.x;
    int m0 = blockIdx.y * 64, n0 = blockIdx.x * 64;
    int tr = tid >> 4, tc = tid & 15;
    float acc[4][4] = {};
    for (int k0 = 0; k0 < 512; k0 += 16){
        int r = tid & 63, kq = (tid >> 6)*4;
        float4 av = *(const float4*)&A[(size_t)(m0 + r)*lda + k0 + kq];
        As[kq+0][r] = av.x; As[kq+1][r] = av.y; As[kq+2][r] = av.z; As[kq+3][r] = av.w;
        int kb = tid >> 4, cb = (tid & 15)*4;
        *(float4*)&Bs[kb][cb] = *(const float4*)&B[(size_t)(k0 + kb)*512 + n0 + cb];
        __syncthreads();
        #pragma unroll
        for (int kk = 0; kk < 16; kk++){
            float a[4], bv[4];
            *(float4*)a  = *(const float4*)&As[kk][tr*4];
            *(float4*)bv = *(const float4*)&Bs[kk][tc*4];
            #pragma unroll
            for (int i = 0; i < 4; i++)
                #pragma unroll
                for (int j = 0; j < 4; j++) acc[i][j] += a[i]*bv[j];
        }
        __syncthreads();
    }
    #pragma unroll
    for (int i = 0; i < 4; i++)
        #pragma unroll
        for (int j = 0; j < 4; j++)
            C[(size_t)(m0 + tr*4 + i)*ldc + n0 + tc*4 + j] = acc[i][j];
}

__global__ void k_fold_u(const float* __restrict__ phone_w, const float* __restrict__ phone_b,
                         const float* __restrict__ imu_w,   const float* __restrict__ imu_b,
                         const float* __restrict__ out_proj_b)
{
    int idx = blockIdx.x * blockDim.x + threadIdx.x;
    if (idx >= 1024) return;
    int d = idx >> 9, j = idx & 511;
    const float* W  = d ? imu_w : phone_w;
    const float* bb = d ? imu_b : phone_b;
    float s = bb[j];
    for (int l = 0; l < 512; l++) s += W[j * 512 + l] * out_proj_b[l];
    g_u[idx] = s;
}

__global__ void k_fold_bconst(const float* __restrict__ output_w,
                              const float* __restrict__ output_b,
                              float* __restrict__ d_avg)
{
    int o = blockIdx.x * blockDim.x + threadIdx.x;
    if (o < 64) d_avg[o] = 0.f;
    if (o >= 512) return;
    float s = output_b[o];
    for (int j = 0; j < 512; j++) {
        s += output_w[o * 1024 + j]       * g_u[j];
        s += output_w[o * 1024 + 512 + j] * g_u[512 + j];
    }
    g_bconst[o] = s;
}

// =========================================================================
extern "C" void kernel_launch(void* const* d_in, const int* in_sizes, int n_in,
                              void* d_out, int out_size)
{
    (void)in_sizes; (void)n_in; (void)out_size;
    const float* x     = (const float*)d_in[0];
    const float* emb   = (const float*)d_in[1];
    const float* in_w  = (const float*)d_in[2];
    const float* in_b  = (const float*)d_in[3];
    const float* out_w = (const float*)d_in[4];
    const float* out_b = (const float*)d_in[5];
    const float* ph_w  = (const float*)d_in[6];
    const float* ph_b  = (const float*)d_in[7];
    const float* im_w  = (const float*)d_in[8];
    const float* im_b  = (const float*)d_in[9];
    const float* o2_w  = (const float*)d_in[10];
    const float* o2_b  = (const float*)d_in[11];
    float* out   = (float*)d_out;
    float* d_avg = out + (size_t)16 * 512 * 2048;

    // weight folding: T = {phone,imu}_w @ out_proj_w ; M = o2_w{L,R} @ T
    k_fold<<<dim3(8,8,2), 256>>>(ph_w, im_w, 512, out_w, 0, 0);
    k_fold<<<dim3(8,8,2), 256>>>(o2_w, o2_w + 512, 1024, nullptr, 1, 1);
    k_fold_u<<<4, 256>>>(ph_w, ph_b, im_w, im_b, out_b);
    k_fold_bconst<<<2, 256>>>(o2_w, o2_b, d_avg);
    k_split<<<(1536*512 + 255)/256, 256>>>(in_w, 0, 1536*512);
    k_split<<<(512*1024 + 255)/256, 256>>>(nullptr, 1, 512*1024);
    k_prep_x<<<dim3(64, 16, 32), 256>>>(x, emb);

    // main pipeline (HMMA GEMMs)
    k_mma <<<dim3(12, 512), 256>>>(0, in_b, nullptr);   // QKV: n2 x 1536
    k_attn<<<Nn/2, 256>>>(d_avg);
    k_mma <<<dim3(256, 4), 256>>>(1, nullptr, out);     // out: o x tokens
}

// round 14
// speedup vs baseline: 3.0218x; 1.5388x over previous
#include <cuda_runtime.h>
#include <cuda_fp16.h>
#include <stdint.h>
#include <math.h>

#define Nn 32768
#define N2 65536

// ---------------- device scratch (no allocations allowed) ----------------
__device__ __align__(256) __half g_xh[(size_t)N2*512];
__device__ __align__(256) __half g_xl[(size_t)N2*512];
__device__ __align__(256) __half g_wh[1536*512];
__device__ __align__(256) float g_QKV[(size_t)N2*1536];
__device__ __align__(256) __half g_ch[(size_t)Nn*1024];
__device__ __align__(256) float g_tmp[2*512*512];
__device__ __align__(256) float g_Mcat[512*1024];
__device__ __align__(256) __half g_mh[512*1024];
__device__ __align__(256) __half g_ml[512*1024];
__device__ float g_u[1024];
__device__ float g_bconst[512];

// ---------------- PTX helpers (sm_80-baseline ISA only) ----------------
__device__ __forceinline__ unsigned smem_u32(const void* p){
    unsigned a;
    asm("{ .reg .u64 t; cvta.to.shared.u64 t, %1; cvt.u32.u64 %0, t; }" : "=r"(a) : "l"(p));
    return a;
}
#define CP16(smem_addr, gptr) \
    asm volatile("cp.async.cg.shared.global [%0], [%1], 16;" :: "r"(smem_addr), "l"(gptr))
#define CP_COMMIT() asm volatile("cp.async.commit_group;" ::: "memory")
#define LDSM4(r, addr) \
    asm volatile("ldmatrix.sync.aligned.m8n8.x4.shared.b16 {%0,%1,%2,%3}, [%4];" \
        : "=r"((r)[0]), "=r"((r)[1]), "=r"((r)[2]), "=r"((r)[3]) : "r"(addr))
#define MMA16816(d, a, b0, b1) \
    asm volatile("mma.sync.aligned.m16n8k16.row.col.f32.f16.f16.f32 " \
        "{%0,%1,%2,%3}, {%4,%5,%6,%7}, {%8,%9}, {%0,%1,%2,%3};" \
        : "+f"((d)[0]), "+f"((d)[1]), "+f"((d)[2]), "+f"((d)[3]) \
        : "r"((a)[0]), "r"((a)[1]), "r"((a)[2]), "r"((a)[3]), "r"(b0), "r"(b1))

// Tile geometry: CTA 128(M) x 128(N), K-chunk 32. Smem rows padded to 80B.
#define LDS_ROW 80
#define TILE_BYTES (128*LDS_ROW)        // 10240 per matrix
#define BUF_BYTES  (2*TILE_BYTES)       // A + B per buffer

// =========================================================================
// Unified HMMA GEMM. D[m][n] = sum_k A[m][k]*B[n][k], fp16 2-segment split:
//   seg0 = Ah*Bh, seg1 = Al*Bh  (dropped Ah*Bl ~ 1.4e-4 rel)
// mode 0: A = xe (M=n2 rows), B = in_proj W (N=j)  -> QKV[n2][j] + bias[j]
// mode 1: A = Mcat (M=o),     B = ctx (N=token)    -> out[b][o][t] + bconst[o]
// =========================================================================
__global__ __launch_bounds__(256) void k_mma(int mode, const float* __restrict__ bias,
                                             float* __restrict__ out)
{
    __shared__ __align__(128) char smem[2*BUF_BYTES];
    unsigned sb = smem_u32(smem);
    int tid = threadIdx.x, wid = tid >> 5, lane = tid & 31;

    const __half* Ah = mode ? g_mh : g_xh;
    const __half* Al = mode ? g_ml : g_xl;
    const __half* Bh = mode ? g_ch : g_wh;
    int ldk  = mode ? 1024 : 512;
    int per  = mode ? 32 : 16;          // K-chunks per segment
    int nblk = 2 * per;

    int m0 = blockIdx.y * 128;
    int n0 = blockIdx.x * 128;

    // cp.async thread mapping: 2 rows per matrix per thread
    int cr = tid >> 2, cc = tid & 3;    // row 0..63 (+64), 16B col 0..3

    float acc[2][8][4];
    #pragma unroll
    for (int mt = 0; mt < 2; mt++)
        #pragma unroll
        for (int nt = 0; nt < 8; nt++)
            #pragma unroll
            for (int i = 0; i < 4; i++) acc[mt][nt][i] = 0.f;

    int wm = wid >> 1, wn = wid & 1;    // warp grid 4x2 -> warp tile 32x64

    // ---- prefetch chunk 0 ----
    {
        unsigned sa = sb, sB = sb + TILE_BYTES;
        #pragma unroll
        for (int i = 0; i < 2; i++){
            int r = cr + i*64;
            CP16(sa + r*LDS_ROW + cc*16, Ah + (size_t)(m0 + r)*ldk + cc*8);
            CP16(sB + r*LDS_ROW + cc*16, Bh + (size_t)(n0 + r)*ldk + cc*8);
        }
        CP_COMMIT();
    }

    for (int blk = 0; blk < nblk; blk++){
        int buf = blk & 1;
        if (blk + 1 < nblk){
            int nb  = blk + 1;
            int seg = nb / per, k0 = (nb % per) * 32;
            const __half* Ap = seg ? Al : Ah;
            unsigned sa = sb + (buf^1)*BUF_BYTES, sB = sa + TILE_BYTES;
            #pragma unroll
            for (int i = 0; i < 2; i++){
                int r = cr + i*64;
                CP16(sa + r*LDS_ROW + cc*16, Ap + (size_t)(m0 + r)*ldk + k0 + cc*8);
                CP16(sB + r*LDS_ROW + cc*16, Bh + (size_t)(n0 + r)*ldk + k0 + cc*8);
            }
            CP_COMMIT();
            asm volatile("cp.async.wait_group 1;" ::: "memory");
        } else {
            asm volatile("cp.async.wait_group 0;" ::: "memory");
        }
        __syncthreads();

        // ---- compute chunk (2 x k16) ----
        unsigned sa = sb + buf*BUF_BYTES, sB = sa + TILE_BYTES;
        int lrow = lane & 15, lcol = lane >> 4;
        #pragma unroll
        for (int kk = 0; kk < 2; kk++){
            unsigned ra[2][4], rb[4][4];
            #pragma unroll
            for (int mt = 0; mt < 2; mt++){
                unsigned ad = sa + (wm*32 + mt*16 + lrow)*LDS_ROW + (kk*2 + lcol)*16;
                LDSM4(ra[mt], ad);
            }
            #pragma unroll
            for (int p = 0; p < 4; p++){
                unsigned ad = sB + (wn*64 + p*16 + lrow)*LDS_ROW + (kk*2 + lcol)*16;
                LDSM4(rb[p], ad);
            }
            #pragma unroll
            for (int mt = 0; mt < 2; mt++)
                #pragma unroll
                for (int nt = 0; nt < 8; nt++){
                    int p = nt >> 1, w = nt & 1;
                    MMA16816(acc[mt][nt], ra[mt], rb[p][w], rb[p][w + 2]);
                }
        }
        __syncthreads();
    }

    // ---- epilogue: float2 stores along contiguous N ----
    int tr = lane >> 2, tc = lane & 3;
    #pragma unroll
    for (int mt = 0; mt < 2; mt++){
        #pragma unroll
        for (int nt = 0; nt < 8; nt++){
            float* d = acc[mt][nt];
            int gm0 = m0 + wm*32 + mt*16 + tr;
            int gn  = n0 + wn*64 + nt*8 + tc*2;
            if (mode == 0){
                float2 bv = *(const float2*)&bias[gn];
                float2 v0 = { d[0] + bv.x, d[1] + bv.y };
                float2 v1 = { d[2] + bv.x, d[3] + bv.y };
                *(float2*)&g_QKV[(size_t)gm0*1536 + gn]       = v0;
                *(float2*)&g_QKV[(size_t)(gm0+8)*1536 + gn]   = v1;
            } else {
                int b = gn >> 11, t = gn & 2047;
                float b0 = g_bconst[gm0], b1 = g_bconst[gm0 + 8];
                float* ob = out + (size_t)b*1048576 + t;
                float2 v0 = { d[0] + b0, d[1] + b0 };
                float2 v1 = { d[2] + b1, d[3] + b1 };
                *(float2*)&ob[(size_t)gm0*2048]     = v0;
                *(float2*)&ob[(size_t)(gm0+8)*2048] = v1;
            }
        }
    }
}

// =========================================================================
// Attention (fp32 SIMT): 2x2 softmax per (token, head); ctx -> fp16 (B op)
// =========================================================================
__global__ __launch_bounds__(256) void k_attn(float* __restrict__ d_avg)
{
    __shared__ float sp[4];
    int tid = threadIdx.x;
    if (tid < 4) sp[tid] = 0.f;
    __syncthreads();

    int n    = blockIdx.x * 2 + (tid >> 7);
    int h    = (tid >> 5) & 3;
    int lane = tid & 31;

    const float* base = g_QKV + (size_t)(2 * n) * 1536 + h * 128 + lane * 4;
    float4 q0  = *(const float4*)(base);
    float4 q1  = *(const float4*)(base + 1536);
    float4 k0v = *(const float4*)(base + 512);
    float4 k1v = *(const float4*)(base + 512 + 1536);
    float4 v0  = *(const float4*)(base + 1024);
    float4 v1  = *(const float4*)(base + 1024 + 1536);

    float s00 = q0.x*k0v.x + q0.y*k0v.y + q0.z*k0v.z + q0.w*k0v.w;
    float s01 = q0.x*k1v.x + q0.y*k1v.y + q0.z*k1v.z + q0.w*k1v.w;
    float s10 = q1.x*k0v.x + q1.y*k0v.y + q1.z*k0v.z + q1.w*k0v.w;
    float s11 = q1.x*k1v.x + q1.y*k1v.y + q1.z*k1v.z + q1.w*k1v.w;
    #pragma unroll
    for (int off = 16; off; off >>= 1) {
        s00 += __shfl_xor_sync(0xffffffffu, s00, off);
        s01 += __shfl_xor_sync(0xffffffffu, s01, off);
        s10 += __shfl_xor_sync(0xffffffffu, s10, off);
        s11 += __shfl_xor_sync(0xffffffffu, s11, off);
    }
    const float sc = 0.08838834764831845f;
    s00 *= sc; s01 *= sc; s10 *= sc; s11 *= sc;

    float m0 = fmaxf(s00, s01);
    float e00 = expf(s00 - m0), e01 = expf(s01 - m0);
    float r0 = 1.f / (e00 + e01);
    float p00 = e00 * r0, p01 = e01 * r0;
    float m1 = fmaxf(s10, s11);
    float e10 = expf(s10 - m1), e11 = expf(s11 - m1);
    float r1 = 1.f / (e10 + e11);
    float p10 = e10 * r1, p11 = e11 * r1;

    float c0[4], c1[4];
    c0[0] = p00*v0.x + p01*v1.x; c0[1] = p00*v0.y + p01*v1.y;
    c0[2] = p00*v0.z + p01*v1.z; c0[3] = p00*v0.w + p01*v1.w;
    c1[0] = p10*v0.x + p11*v1.x; c1[1] = p10*v0.y + p11*v1.y;
    c1[2] = p10*v0.z + p11*v1.z; c1[3] = p10*v0.w + p11*v1.w;

    int cb = n * 1024 + h * 128 + lane * 4;   // ctx row = token, 1024-wide [dev0|dev1]
    #pragma unroll
    for (int dv = 0; dv < 2; dv++){
        const float* cv = dv ? c1 : c0;
        size_t idx = (size_t)cb + dv * 512;
        __half hh[4];
        #pragma unroll
        for (int i = 0; i < 4; i++) hh[i] = __float2half(cv[i]);
        *(uint2*)(&g_ch[idx]) = *(uint2*)hh;
    }

    if (lane == 0) {
        atomicAdd(&sp[0], p00);
        atomicAdd(&sp[1], p01);
        atomicAdd(&sp[2], p10);
        atomicAdd(&sp[3], p11);
    }
    __syncthreads();
    if (tid < 4) {
        int b = (blockIdx.x * 2) >> 11;
        atomicAdd(&d_avg[b * 4 + tid], sp[tid] * (1.0f / 8192.0f));
    }
}

// =========================================================================
// Prep: xe = transpose(x) + emb -> fp16 hi/lo, rows n2 = 2*(b*2048+t)+d
// =========================================================================
__global__ __launch_bounds__(256) void k_prep_x(const float* __restrict__ x,
                                                const float* __restrict__ emb)
{
    __shared__ float sm[32][33];
    int tx = threadIdx.x & 31, ty = threadIdx.x >> 5;
    int t0 = blockIdx.x * 32, c0 = blockIdx.y * 32;
    int b = blockIdx.z >> 1, d = blockIdx.z & 1;
    #pragma unroll
    for (int i = 0; i < 4; i++){
        int c = c0 + ty + i*8;
        sm[ty + i*8][tx] = x[((size_t)(b*512 + c)*2 + d)*2048 + t0 + tx];
    }
    __syncthreads();
    #pragma unroll
    for (int i = 0; i < 4; i++){
        int t = t0 + ty + i*8;
        int c = c0 + tx;
        float v = sm[tx][ty + i*8] + emb[d*512 + c];
        __half h = __float2half(v);
        size_t idx = (size_t)(2*(b*2048 + t) + d)*512 + c;
        g_xh[idx] = h;
        g_xl[idx] = __float2half(v - __half2float(h));
    }
}

// split fp32 -> fp16. which 0: in_w -> wh (hi only, B operand)
//                     which 1: g_Mcat -> mh/ml (A operand, hi+lo)
__global__ void k_split(const float* __restrict__ srcp, int which, int n)
{
    int i = blockIdx.x * 256 + threadIdx.x;
    if (i >= n) return;
    if (which){
        float v = g_Mcat[i];
        __half h = __float2half(v);
        g_mh[i] = h;
        g_ml[i] = __float2half(v - __half2float(h));
    } else {
        g_wh[i] = __float2half(srcp[i]);
    }
}

// =========================================================================
// Fold: C[m,n] = sum_k A[m*lda+k]*B[k*512+n], 64x64 tile, 4x4/thread, z-batched
// =========================================================================
__global__ __launch_bounds__(256) void k_fold(const float* __restrict__ A0,
                                              const float* __restrict__ A1, int lda,
                                              const float* __restrict__ Bext,
                                              int useTmp, int toMcat)
{
    __shared__ float As[16][68], Bs[16][68];
    int z = blockIdx.z;
    const float* A = z ? A1 : A0;
    const float* B = useTmp ? (g_tmp + z*262144) : Bext;
    float* C; int ldc;
    if (toMcat){ C = g_Mcat + z*512; ldc = 1024; }
    else       { C = g_tmp + z*262144; ldc = 512; }

    int tid = threadIdx.x;
    int m0 = blockIdx.y * 64, n0 = blockIdx.x * 64;
    int tr = tid >> 4, tc = tid & 15;
    float acc[4][4] = {};
    for (int k0 = 0; k0 < 512; k0 += 16){
        int r = tid & 63, kq = (tid >> 6)*4;
        float4 av = *(const float4*)&A[(size_t)(m0 + r)*lda + k0 + kq];
        As[kq+0][r] = av.x; As[kq+1][r] = av.y; As[kq+2][r] = av.z; As[kq+3][r] = av.w;
        int kb = tid >> 4, cb = (tid & 15)*4;
        *(float4*)&Bs[kb][cb] = *(const float4*)&B[(size_t)(k0 + kb)*512 + n0 + cb];
        __syncthreads();
        #pragma unroll
        for (int kk = 0; kk < 16; kk++){
            float a[4], bv[4];
            *(float4*)a  = *(const float4*)&As[kk][tr*4];
            *(float4*)bv = *(const float4*)&Bs[kk][tc*4];
            #pragma unroll
            for (int i = 0; i < 4; i++)
                #pragma unroll
                for (int j = 0; j < 4; j++) acc[i][j] += a[i]*bv[j];
        }
        __syncthreads();
    }
    #pragma unroll
    for (int i = 0; i < 4; i++)
        #pragma unroll
        for (int j = 0; j < 4; j++)
            C[(size_t)(m0 + tr*4 + i)*ldc + n0 + tc*4 + j] = acc[i][j];
}

// u[d][j] = W_d[j,:].out_proj_b + b_d[j] — one warp per output, shuffle reduce
__global__ __launch_bounds__(256) void k_fold_u(const float* __restrict__ phone_w,
                                                const float* __restrict__ phone_b,
                                                const float* __restrict__ imu_w,
                                                const float* __restrict__ imu_b,
                                                const float* __restrict__ out_proj_b)
{
    int gid  = blockIdx.x * 256 + threadIdx.x;
    int gw   = gid >> 5, lane = gid & 31;
    if (gw >= 1024) return;
    int d = gw >> 9, j = gw & 511;
    const float* W = d ? imu_w : phone_w;
    float s = 0.f;
    #pragma unroll 4
    for (int l = lane; l < 512; l += 32) s += W[j*512 + l] * out_proj_b[l];
    #pragma unroll
    for (int off = 16; off; off >>= 1) s += __shfl_xor_sync(0xffffffffu, s, off);
    if (lane == 0) g_u[gw] = s + (d ? imu_b[j] : phone_b[j]);
}

// bconst[o] = output_w[o,:].g_u + output_b[o] — warp per o; zero avg region
__global__ __launch_bounds__(256) void k_fold_bconst(const float* __restrict__ output_w,
                                                     const float* __restrict__ output_b,
                                                     float* __restrict__ d_avg)
{
    int gid = blockIdx.x * 256 + threadIdx.x;
    if (gid < 64) d_avg[gid] = 0.f;
    int gw = gid >> 5, lane = gid & 31;
    if (gw >= 512) return;
    float s = 0.f;
    #pragma unroll 4
    for (int j = lane; j < 1024; j += 32) s += output_w[gw*1024 + j] * g_u[j];
    #pragma unroll
    for (int off = 16; off; off >>= 1) s += __shfl_xor_sync(0xffffffffu, s, off);
    if (lane == 0) g_bconst[gw] = s + output_b[gw];
}

// =========================================================================
extern "C" void kernel_launch(void* const* d_in, const int* in_sizes, int n_in,
                              void* d_out, int out_size)
{
    (void)in_sizes; (void)n_in; (void)out_size;
    const float* x     = (const float*)d_in[0];
    const float* emb   = (const float*)d_in[1];
    const float* in_w  = (const float*)d_in[2];
    const float* in_b  = (const float*)d_in[3];
    const float* out_w = (const float*)d_in[4];
    const float* out_b = (const float*)d_in[5];
    const float* ph_w  = (const float*)d_in[6];
    const float* ph_b  = (const float*)d_in[7];
    const float* im_w  = (const float*)d_in[8];
    const float* im_b  = (const float*)d_in[9];
    const float* o2_w  = (const float*)d_in[10];
    const float* o2_b  = (const float*)d_in[11];
    float* out   = (float*)d_out;
    float* d_avg = out + (size_t)16 * 512 * 2048;

    // weight folding: T = {phone,imu}_w @ out_proj_w ; M = o2_w{L,R} @ T
    k_fold<<<dim3(8,8,2), 256>>>(ph_w, im_w, 512, out_w, 0, 0);
    k_fold<<<dim3(8,8,2), 256>>>(o2_w, o2_w + 512, 1024, nullptr, 1, 1);
    k_fold_u<<<128, 256>>>(ph_w, ph_b, im_w, im_b, out_b);
    k_fold_bconst<<<64, 256>>>(o2_w, o2_b, d_avg);
    k_split<<<(1536*512 + 255)/256, 256>>>(in_w, 0, 1536*512);
    k_split<<<(512*1024 + 255)/256, 256>>>(nullptr, 1, 512*1024);
    k_prep_x<<<dim3(64, 16, 32), 256>>>(x, emb);

    // main pipeline (HMMA GEMMs, fp16 2-segment split)
    k_mma <<<dim3(12, 512), 256>>>(0, in_b, nullptr);   // QKV: n2 x 1536
    k_attn<<<Nn/2, 256>>>(d_avg);
    k_mma <<<dim3(256, 4), 256>>>(1, nullptr, out);     // out: o x tokens
}